// round 1
// baseline (speedup 1.0000x reference)
#include <cuda_runtime.h>
#include <math.h>

#define DD 64
#define U_MAX 100000
#define I_MAX 150000

// ---------------- static scratch (no allocations allowed) ----------------
__device__ float g_u1 [U_MAX * DD];
__device__ float g_u2 [U_MAX * DD];
__device__ float g_i1 [I_MAX * DD];
__device__ float g_i2 [I_MAX * DD];
__device__ float g_Y  [U_MAX * DD];
__device__ float g_nbr[U_MAX * DD];
__device__ float g_c1 [U_MAX * DD];
__device__ float g_c2 [U_MAX * DD];

// ---------------- helpers ----------------
__device__ __forceinline__ void red4(float* p, float4 v) {
    asm volatile("red.global.add.v4.f32 [%0], {%1,%2,%3,%4};"
                 :: "l"(p), "f"(v.x), "f"(v.y), "f"(v.z), "f"(v.w) : "memory");
}

// out[i] = s * in[i]   (float4 granularity)
__global__ void scale_init_kernel(float4* __restrict__ out, const float4* __restrict__ in,
                                  float s, int n4) {
    int i = blockIdx.x * blockDim.x + threadIdx.x;
    if (i < n4) {
        float4 v = in[i];
        v.x *= s; v.y *= s; v.z *= s; v.w *= s;
        out[i] = v;
    }
}

__global__ void zero_kernel(float4* __restrict__ out, int n4) {
    int i = blockIdx.x * blockDim.x + threadIdx.x;
    if (i < n4) out[i] = make_float4(0.f, 0.f, 0.f, 0.f);
}

// Fused bidirectional SpMM over the UI edge list:
//   accu[su[e]] += w[e] * xi[di[e]]       (user <- items)
//   acci[di[e]] += w[e] * xu[su[e]]       (item <- users)
// 16 threads per edge, float4 chunks, vector reductions.
__global__ void spmm_dual_kernel(const int* __restrict__ su, const int* __restrict__ di,
                                 const float* __restrict__ w,
                                 const float* __restrict__ xu, const float* __restrict__ xi,
                                 float* __restrict__ accu, float* __restrict__ acci,
                                 int nnz) {
    long long idx = (long long)blockIdx.x * blockDim.x + threadIdx.x;
    int e = (int)(idx >> 4);
    if (e >= nnz) return;
    int c = (int)idx & 15;
    int s = su[e];
    int d = di[e];
    float we = w[e];

    float4 vi = __ldg((const float4*)(xi + (size_t)d * DD) + c);
    vi.x *= we; vi.y *= we; vi.z *= we; vi.w *= we;
    red4(accu + (size_t)s * DD + c * 4, vi);

    float4 vu = __ldg((const float4*)(xu + (size_t)s * DD) + c);
    vu.x *= we; vu.y *= we; vu.z *= we; vu.w *= we;
    red4(acci + (size_t)d * DD + c * 4, vu);
}

// Single-direction SpMM: acc[src[e]] += w[e] * x[dst[e]]
__global__ void spmm_single_kernel(const int* __restrict__ src, const int* __restrict__ dst,
                                   const float* __restrict__ w, const float* __restrict__ x,
                                   float* __restrict__ acc, int nnz) {
    long long idx = (long long)blockIdx.x * blockDim.x + threadIdx.x;
    int e = (int)(idx >> 4);
    if (e >= nnz) return;
    int c = (int)idx & 15;
    int s = src[e];
    int d = dst[e];
    float we = w[e];
    float4 v = __ldg((const float4*)(x + (size_t)d * DD) + c);
    v.x *= we; v.y *= we; v.z *= we; v.w *= we;
    red4(acc + (size_t)s * DD + c * 4, v);
}

// Y[r,:] = X[r,:] @ W (64x64).  512 threads, 32 rows/block; each warp owns 2 rows;
// each thread owns one float4 column chunk; row value broadcast via shuffles.
__global__ void __launch_bounds__(512) gemm64_kernel(const float* __restrict__ X,
                                                     const float* __restrict__ W,
                                                     float* __restrict__ Y, int nrows) {
    __shared__ __align__(16) float Ws[64 * 64];
    int tid = threadIdx.x;
    for (int i = tid; i < 64 * 64; i += 512) Ws[i] = W[i];
    __syncthreads();

    int lane = tid & 31;
    int c4 = lane & 15;
    int row = blockIdx.x * 32 + (tid >> 5) * 2 + (lane >> 4);
    int rrow = row < nrows ? row : nrows - 1;

    float4 xv = ((const float4*)(X + (size_t)rrow * DD))[c4];
    float4 z = make_float4(0.f, 0.f, 0.f, 0.f);
#pragma unroll
    for (int k = 0; k < 64; ++k) {
        int srcl = (k >> 2) | (lane & 16);
        float comp = (k & 3) == 0 ? xv.x : (k & 3) == 1 ? xv.y : (k & 3) == 2 ? xv.z : xv.w;
        float xk = __shfl_sync(0xffffffffu, comp, srcl);
        float4 w4 = ((const float4*)(Ws + (k << 6)))[c4];
        z.x += xk * w4.x; z.y += xk * w4.y; z.z += xk * w4.z; z.w += xk * w4.w;
    }
    if (row < nrows) ((float4*)(Y + (size_t)row * DD))[c4] = z;
}

// Fused social gate:
//   new = cur + nbr
//   z   = new @ hoW + hob ; ln = layernorm(z)*g + beta ; v = lrelu(ln) ; gate = sigmoid(v)
//   out = gate*new + (1-gate)*cur
__global__ void __launch_bounds__(512) social_gate_kernel(const float* __restrict__ cur,
                                                          const float* __restrict__ nbr,
                                                          const float* __restrict__ hoW,
                                                          const float* __restrict__ hob,
                                                          const float* __restrict__ hog,
                                                          const float* __restrict__ hobe,
                                                          float* __restrict__ outc, int nrows) {
    __shared__ __align__(16) float Ws[64 * 64];
    __shared__ __align__(16) float bb[64];
    __shared__ __align__(16) float gg[64];
    __shared__ __align__(16) float be[64];
    int tid = threadIdx.x;
    for (int i = tid; i < 64 * 64; i += 512) Ws[i] = hoW[i];
    if (tid < 64) { bb[tid] = hob[tid]; gg[tid] = hog[tid]; be[tid] = hobe[tid]; }
    __syncthreads();

    int lane = tid & 31;
    int c4 = lane & 15;
    int row = blockIdx.x * 32 + (tid >> 5) * 2 + (lane >> 4);
    int rrow = row < nrows ? row : nrows - 1;

    float4 cv = ((const float4*)(cur + (size_t)rrow * DD))[c4];
    float4 nb = ((const float4*)(nbr + (size_t)rrow * DD))[c4];
    float4 nv = make_float4(cv.x + nb.x, cv.y + nb.y, cv.z + nb.z, cv.w + nb.w);

    float4 z = make_float4(0.f, 0.f, 0.f, 0.f);
#pragma unroll
    for (int k = 0; k < 64; ++k) {
        int srcl = (k >> 2) | (lane & 16);
        float comp = (k & 3) == 0 ? nv.x : (k & 3) == 1 ? nv.y : (k & 3) == 2 ? nv.z : nv.w;
        float xk = __shfl_sync(0xffffffffu, comp, srcl);
        float4 w4 = ((const float4*)(Ws + (k << 6)))[c4];
        z.x += xk * w4.x; z.y += xk * w4.y; z.z += xk * w4.z; z.w += xk * w4.w;
    }
    float4 b4 = ((const float4*)bb)[c4];
    z.x += b4.x; z.y += b4.y; z.z += b4.z; z.w += b4.w;

    float s = z.x + z.y + z.z + z.w;
    float q = z.x * z.x + z.y * z.y + z.z * z.z + z.w * z.w;
#pragma unroll
    for (int mk = 1; mk < 16; mk <<= 1) {
        s += __shfl_xor_sync(0xffffffffu, s, mk);
        q += __shfl_xor_sync(0xffffffffu, q, mk);
    }
    float mu = s * (1.f / 64.f);
    float var = q * (1.f / 64.f) - mu * mu;
    float rstd = rsqrtf(var + 1e-5f);

    float4 g4 = ((const float4*)gg)[c4];
    float4 e4 = ((const float4*)be)[c4];

    float4 o;
    {
        float ln = (z.x - mu) * rstd * g4.x + e4.x;
        float v = ln > 0.f ? ln : 0.01f * ln;
        float gt = 1.f / (1.f + expf(-v));
        o.x = gt * nv.x + (1.f - gt) * cv.x;
    }
    {
        float ln = (z.y - mu) * rstd * g4.y + e4.y;
        float v = ln > 0.f ? ln : 0.01f * ln;
        float gt = 1.f / (1.f + expf(-v));
        o.y = gt * nv.y + (1.f - gt) * cv.y;
    }
    {
        float ln = (z.z - mu) * rstd * g4.z + e4.z;
        float v = ln > 0.f ? ln : 0.01f * ln;
        float gt = 1.f / (1.f + expf(-v));
        o.z = gt * nv.z + (1.f - gt) * cv.z;
    }
    {
        float ln = (z.w - mu) * rstd * g4.w + e4.w;
        float v = ln > 0.f ? ln : 0.01f * ln;
        float gt = 1.f / (1.f + expf(-v));
        o.w = gt * nv.w + (1.f - gt) * cv.w;
    }
    if (row < nrows) ((float4*)(outc + (size_t)row * DD))[c4] = o;
}

// Final: gather batch rows, metapath fusion (128x64 GEMM + LN + lrelu), dot score.
__global__ void __launch_bounds__(64) score_kernel(const int* __restrict__ users,
                                                   const int* __restrict__ pos,
                                                   const float* __restrict__ e0u,
                                                   const float* __restrict__ u1,
                                                   const float* __restrict__ u2,
                                                   const float* __restrict__ c1,
                                                   const float* __restrict__ c2,
                                                   const float* __restrict__ e0i,
                                                   const float* __restrict__ i1,
                                                   const float* __restrict__ i2,
                                                   const float* __restrict__ lw,
                                                   const float* __restrict__ mpW,
                                                   const float* __restrict__ mpb,
                                                   const float* __restrict__ mpg,
                                                   const float* __restrict__ mpbe,
                                                   float* __restrict__ out, int B) {
    int b = blockIdx.x;
    if (b >= B) return;
    int t = threadIdx.x;  // 0..63
    __shared__ float fi[128];
    __shared__ float red[4];

    // softmax over layer_weights[:3]
    float l0 = lw[0], l1 = lw[1], l2 = lw[2];
    float mx = fmaxf(l0, fmaxf(l1, l2));
    float ex0 = expf(l0 - mx), ex1 = expf(l1 - mx), ex2 = expf(l2 - mx);
    float inv = 1.f / (ex0 + ex1 + ex2);
    float nw0 = ex0 * inv, nw1 = ex1 * inv, nw2 = ex2 * inv;

    int u = users[b], p = pos[b];
    size_t uo = (size_t)u * DD + t;
    size_t po = (size_t)p * DD + t;

    fi[t]      = nw0 * e0u[uo] + nw1 * u1[uo] + nw2 * u2[uo];   // user_weighted
    fi[64 + t] = nw0 * u2[uo]  + nw1 * c1[uo] + nw2 * c2[uo];   // social_weighted
    __syncthreads();

    float z = mpb[t];
#pragma unroll 8
    for (int k = 0; k < 128; ++k) z += fi[k] * __ldg(mpW + k * 64 + t);

    float s = z, q = z * z;
#pragma unroll
    for (int mk = 16; mk; mk >>= 1) {
        s += __shfl_xor_sync(0xffffffffu, s, mk);
        q += __shfl_xor_sync(0xffffffffu, q, mk);
    }
    int wid = t >> 5, lane = t & 31;
    if (lane == 0) { red[wid] = s; red[2 + wid] = q; }
    __syncthreads();
    s = red[0] + red[1];
    q = red[2] + red[3];
    float mu = s * (1.f / 64.f);
    float var = q * (1.f / 64.f) - mu * mu;
    float rstd = rsqrtf(var + 1e-5f);
    float ln = (z - mu) * rstd * mpg[t] + mpbe[t];
    float f = ln > 0.f ? ln : 0.01f * ln;

    float iw = nw0 * e0i[po] + nw1 * i1[po] + nw2 * i2[po];
    float pr = f * iw;
#pragma unroll
    for (int mk = 16; mk; mk >>= 1) pr += __shfl_xor_sync(0xffffffffu, pr, mk);
    __syncthreads();
    if (lane == 0) red[wid] = pr;
    __syncthreads();
    if (t == 0) out[b] = red[0] + red[1];
}

// ---------------- host ----------------
extern "C" void kernel_launch(void* const* d_in, const int* in_sizes, int n_in,
                              void* d_out, int out_size) {
    const int*   users  = (const int*)  d_in[0];
    const int*   pos    = (const int*)  d_in[1];
    const int*   ui_src = (const int*)  d_in[2];
    const int*   ui_dst = (const int*)  d_in[3];
    const float* ui_w   = (const float*)d_in[4];
    const int*   s_src  = (const int*)  d_in[5];
    const int*   s_dst  = (const int*)  d_in[6];
    const float* s_w    = (const float*)d_in[7];
    const float* E0u    = (const float*)d_in[8];
    const float* E0i    = (const float*)d_in[9];
    const float* lw     = (const float*)d_in[10];
    const float* Wsoc   = (const float*)d_in[11];
    const float* hoW    = (const float*)d_in[12];
    const float* hob    = (const float*)d_in[13];
    const float* hog    = (const float*)d_in[14];
    const float* hobe   = (const float*)d_in[15];
    const float* mpW    = (const float*)d_in[16];
    const float* mpb    = (const float*)d_in[17];
    const float* mpg    = (const float*)d_in[18];
    const float* mpbe   = (const float*)d_in[19];

    int B      = in_sizes[0];
    int nnz_ui = in_sizes[4];
    int nnz_s  = in_sizes[7];
    int U      = in_sizes[8] / DD;
    int I      = in_sizes[9] / DD;

    float *u1, *u2, *i1, *i2, *Y, *nbr, *c1, *c2;
    cudaGetSymbolAddress((void**)&u1,  g_u1);
    cudaGetSymbolAddress((void**)&u2,  g_u2);
    cudaGetSymbolAddress((void**)&i1,  g_i1);
    cudaGetSymbolAddress((void**)&i2,  g_i2);
    cudaGetSymbolAddress((void**)&Y,   g_Y);
    cudaGetSymbolAddress((void**)&nbr, g_nbr);
    cudaGetSymbolAddress((void**)&c1,  g_c1);
    cudaGetSymbolAddress((void**)&c2,  g_c2);

    int u4 = U * DD / 4, i4 = I * DD / 4;
    int gu4 = (u4 + 255) / 256, gi4 = (i4 + 255) / 256;
    long long wui = (long long)nnz_ui * 16;
    long long ws  = (long long)nnz_s * 16;
    int g_ui = (int)((wui + 255) / 256);
    int g_s  = (int)((ws + 255) / 256);
    int g_rows = (U + 31) / 32;

    // ---- LightGCN layer 1 (residual folded into init) ----
    scale_init_kernel<<<gu4, 256>>>((float4*)u1, (const float4*)E0u, 0.1f, u4);
    scale_init_kernel<<<gi4, 256>>>((float4*)i1, (const float4*)E0i, 0.1f, i4);
    spmm_dual_kernel<<<g_ui, 256>>>(ui_src, ui_dst, ui_w, E0u, E0i, u1, i1, nnz_ui);

    // ---- LightGCN layer 2 ----
    scale_init_kernel<<<gu4, 256>>>((float4*)u2, (const float4*)E0u, 0.1f, u4);
    scale_init_kernel<<<gi4, 256>>>((float4*)i2, (const float4*)E0i, 0.1f, i4);
    spmm_dual_kernel<<<g_ui, 256>>>(ui_src, ui_dst, ui_w, u1, i1, u2, i2, nnz_ui);

    // ---- Social layer 1 (cur = u2) ----
    gemm64_kernel<<<g_rows, 512>>>(u2, Wsoc, Y, U);
    zero_kernel<<<gu4, 256>>>((float4*)nbr, u4);
    spmm_single_kernel<<<g_s, 256>>>(s_src, s_dst, s_w, Y, nbr, nnz_s);
    social_gate_kernel<<<g_rows, 512>>>(u2, nbr, hoW, hob, hog, hobe, c1, U);

    // ---- Social layer 2 (cur = c1) ----
    gemm64_kernel<<<g_rows, 512>>>(c1, Wsoc + 64 * 64, Y, U);
    zero_kernel<<<gu4, 256>>>((float4*)nbr, u4);
    spmm_single_kernel<<<g_s, 256>>>(s_src, s_dst, s_w, Y, nbr, nnz_s);
    social_gate_kernel<<<g_rows, 512>>>(c1, nbr, hoW, hob, hog, hobe, c2, U);

    // ---- Fusion + scoring, batch rows only ----
    score_kernel<<<B, 64>>>(users, pos, E0u, u1, u2, c1, c2, E0i, i1, i2,
                            lw, mpW, mpb, mpg, mpbe, (float*)d_out, B);
}

// round 2
// speedup vs baseline: 1.2848x; 1.2848x over previous
#include <cuda_runtime.h>
#include <math.h>

#define DD 64
#define U_MAX 100000
#define I_MAX 150000
#define NNZ_UI_MAX 2000000
#define NNZ_S_MAX 1000000

// ---------------- static scratch (no allocations allowed) ----------------
__device__ float g_u1 [U_MAX * DD];
__device__ float g_u2 [U_MAX * DD];
__device__ float g_i1 [I_MAX * DD];
__device__ float g_i2 [I_MAX * DD];
__device__ float g_nbr[U_MAX * DD];
__device__ float g_c1 [U_MAX * DD];
__device__ float g_c2 [U_MAX * DD];

__device__ int  g_deg_u[U_MAX];
__device__ int  g_deg_i[I_MAX];
__device__ int  g_deg_s[U_MAX];
__device__ int  g_rp_u [U_MAX + 1];
__device__ int  g_rp_i [I_MAX + 1];
__device__ int  g_rp_s [U_MAX + 1];
__device__ int  g_cur_u[U_MAX];
__device__ int  g_cur_i[I_MAX];
__device__ int  g_cur_s[U_MAX];
__device__ int  g_aux  [1024];
__device__ int2 g_eu[NNZ_UI_MAX];   // user-side CSR of UI graph: (item, w)
__device__ int2 g_ei[NNZ_UI_MAX];   // item-side CSR of UI graph: (user, w)
__device__ int2 g_es[NNZ_S_MAX];    // social CSR: (src_col, w)

// ---------------- CSR build ----------------
__global__ void count_ui_kernel(const int* __restrict__ su, const int* __restrict__ di,
                                int* __restrict__ du, int* __restrict__ dI, int nnz) {
    int e = blockIdx.x * blockDim.x + threadIdx.x;
    if (e >= nnz) return;
    atomicAdd(du + su[e], 1);
    atomicAdd(dI + di[e], 1);
}

__global__ void count_s_kernel(const int* __restrict__ src, int* __restrict__ ds, int nnz) {
    int e = blockIdx.x * blockDim.x + threadIdx.x;
    if (e >= nnz) return;
    atomicAdd(ds + src[e], 1);
}

// block-local exclusive scan; rp[i] = local exclusive, aux[b] = block total
__global__ void __launch_bounds__(1024) scan1_kernel(const int* __restrict__ deg,
                                                     int* __restrict__ rp,
                                                     int* __restrict__ aux, int n) {
    __shared__ int s[1024];
    int tid = threadIdx.x;
    int i = blockIdx.x * 1024 + tid;
    int v = (i < n) ? deg[i] : 0;
    s[tid] = v;
    __syncthreads();
#pragma unroll
    for (int off = 1; off < 1024; off <<= 1) {
        int t = (tid >= off) ? s[tid - off] : 0;
        __syncthreads();
        s[tid] += t;
        __syncthreads();
    }
    if (i < n) rp[i] = s[tid] - v;
    if (tid == 1023) aux[blockIdx.x] = s[1023];
}

// exclusive scan of aux (nb <= 256), single block
__global__ void __launch_bounds__(256) scan2_kernel(int* __restrict__ aux, int nb) {
    __shared__ int s[256];
    int tid = threadIdx.x;
    int v = (tid < nb) ? aux[tid] : 0;
    s[tid] = v;
    __syncthreads();
#pragma unroll
    for (int off = 1; off < 256; off <<= 1) {
        int t = (tid >= off) ? s[tid - off] : 0;
        __syncthreads();
        s[tid] += t;
        __syncthreads();
    }
    if (tid < nb) aux[tid] = s[tid] - v;
}

// rp[i] += aux[block]; cursor copy; rp[n] = nnz
__global__ void scan3_kernel(int* __restrict__ rp, const int* __restrict__ aux,
                             int* __restrict__ cur, int n, int nnz) {
    int i = blockIdx.x * blockDim.x + threadIdx.x;
    if (i < n) {
        int v = rp[i] + aux[i >> 10];
        rp[i] = v;
        cur[i] = v;
    }
    if (i == 0) rp[n] = nnz;
}

__global__ void scatter_ui_kernel(const int* __restrict__ su, const int* __restrict__ di,
                                  const float* __restrict__ w,
                                  int* __restrict__ cu, int* __restrict__ ci,
                                  int2* __restrict__ eu, int2* __restrict__ ei, int nnz) {
    int e = blockIdx.x * blockDim.x + threadIdx.x;
    if (e >= nnz) return;
    int s = su[e], d = di[e];
    int wb = __float_as_int(w[e]);
    int p = atomicAdd(cu + s, 1);
    eu[p] = make_int2(d, wb);
    int q = atomicAdd(ci + d, 1);
    ei[q] = make_int2(s, wb);
}

__global__ void scatter_s_kernel(const int* __restrict__ src, const int* __restrict__ dst,
                                 const float* __restrict__ w,
                                 int* __restrict__ cs, int2* __restrict__ es, int nnz) {
    int e = blockIdx.x * blockDim.x + threadIdx.x;
    if (e >= nnz) return;
    int p = atomicAdd(cs + src[e], 1);
    es[p] = make_int2(dst[e], __float_as_int(w[e]));
}

// ---------------- gather SpMM: out[r] = scale*e0[r] + sum_j w_j * x[col_j] ----------------
// one warp per row, each lane owns a float2 (64 floats / 32 lanes)
__global__ void __launch_bounds__(256) gather_kernel(const int* __restrict__ rp,
                                                     const int2* __restrict__ ed,
                                                     const float* __restrict__ x,
                                                     const float* __restrict__ e0, float scale,
                                                     float* __restrict__ out, int nrows) {
    int row = blockIdx.x * 8 + (threadIdx.x >> 5);
    if (row >= nrows) return;
    int lane = threadIdx.x & 31;
    const float2* x2 = (const float2*)x;
    size_t ro = (size_t)row * 32 + lane;

    float2 acc;
    if (e0) {
        float2 v = __ldg((const float2*)e0 + ro);
        acc.x = scale * v.x; acc.y = scale * v.y;
    } else {
        acc = make_float2(0.f, 0.f);
    }

    int j = __ldg(rp + row), end = __ldg(rp + row + 1);
    for (; j + 2 <= end; j += 2) {
        int2 a = __ldg(ed + j);
        int2 b = __ldg(ed + j + 1);
        float2 va = __ldg(x2 + (size_t)a.x * 32 + lane);
        float2 vb = __ldg(x2 + (size_t)b.x * 32 + lane);
        float wa = __int_as_float(a.y), wb = __int_as_float(b.y);
        acc.x += wa * va.x; acc.y += wa * va.y;
        acc.x += wb * vb.x; acc.y += wb * vb.y;
    }
    if (j < end) {
        int2 a = __ldg(ed + j);
        float2 va = __ldg(x2 + (size_t)a.x * 32 + lane);
        float wa = __int_as_float(a.y);
        acc.x += wa * va.x; acc.y += wa * va.y;
    }
    ((float2*)out)[ro] = acc;
}

// ---------------- fused social layer ----------------
//   nbr = nbr0 @ Wsoc_l            (linearity: A@(X W) == (A@X) W)
//   new = cur + nbr
//   z   = new @ hoW + hob ; ln = LN(z)*g + beta ; gate = sigmoid(lrelu(ln))
//   out = gate*new + (1-gate)*cur
__global__ void __launch_bounds__(512) social_gate2_kernel(const float* __restrict__ cur,
                                                           const float* __restrict__ nbr0,
                                                           const float* __restrict__ Wsoc_l,
                                                           const float* __restrict__ hoW,
                                                           const float* __restrict__ hob,
                                                           const float* __restrict__ hog,
                                                           const float* __restrict__ hobe,
                                                           float* __restrict__ outc, int nrows) {
    __shared__ __align__(16) float Ws1[64 * 64];
    __shared__ __align__(16) float Ws2[64 * 64];
    __shared__ __align__(16) float bb[64];
    __shared__ __align__(16) float gg[64];
    __shared__ __align__(16) float be[64];
    int tid = threadIdx.x;
    for (int i = tid; i < 64 * 64; i += 512) { Ws1[i] = Wsoc_l[i]; Ws2[i] = hoW[i]; }
    if (tid < 64) { bb[tid] = hob[tid]; gg[tid] = hog[tid]; be[tid] = hobe[tid]; }
    __syncthreads();

    int lane = tid & 31;
    int c4 = lane & 15;
    int row = blockIdx.x * 32 + (tid >> 5) * 2 + (lane >> 4);
    int rrow = row < nrows ? row : nrows - 1;

    float4 n0 = ((const float4*)(nbr0 + (size_t)rrow * DD))[c4];
    float4 cv = ((const float4*)(cur + (size_t)rrow * DD))[c4];

    // GEMM1: nbr = nbr0 @ Ws1
    float4 nb = make_float4(0.f, 0.f, 0.f, 0.f);
#pragma unroll
    for (int k = 0; k < 64; ++k) {
        int srcl = (k >> 2) | (lane & 16);
        float comp = (k & 3) == 0 ? n0.x : (k & 3) == 1 ? n0.y : (k & 3) == 2 ? n0.z : n0.w;
        float xk = __shfl_sync(0xffffffffu, comp, srcl);
        float4 w4 = ((const float4*)(Ws1 + (k << 6)))[c4];
        nb.x += xk * w4.x; nb.y += xk * w4.y; nb.z += xk * w4.z; nb.w += xk * w4.w;
    }
    float4 nv = make_float4(cv.x + nb.x, cv.y + nb.y, cv.z + nb.z, cv.w + nb.w);

    // GEMM2: z = nv @ Ws2 + b
    float4 z = make_float4(0.f, 0.f, 0.f, 0.f);
#pragma unroll
    for (int k = 0; k < 64; ++k) {
        int srcl = (k >> 2) | (lane & 16);
        float comp = (k & 3) == 0 ? nv.x : (k & 3) == 1 ? nv.y : (k & 3) == 2 ? nv.z : nv.w;
        float xk = __shfl_sync(0xffffffffu, comp, srcl);
        float4 w4 = ((const float4*)(Ws2 + (k << 6)))[c4];
        z.x += xk * w4.x; z.y += xk * w4.y; z.z += xk * w4.z; z.w += xk * w4.w;
    }
    float4 b4 = ((const float4*)bb)[c4];
    z.x += b4.x; z.y += b4.y; z.z += b4.z; z.w += b4.w;

    // LayerNorm stats over the row's 16 lanes
    float s = z.x + z.y + z.z + z.w;
    float q = z.x * z.x + z.y * z.y + z.z * z.z + z.w * z.w;
#pragma unroll
    for (int mk = 1; mk < 16; mk <<= 1) {
        s += __shfl_xor_sync(0xffffffffu, s, mk);
        q += __shfl_xor_sync(0xffffffffu, q, mk);
    }
    float mu = s * (1.f / 64.f);
    float var = q * (1.f / 64.f) - mu * mu;
    float rstd = rsqrtf(var + 1e-5f);

    float4 g4 = ((const float4*)gg)[c4];
    float4 e4 = ((const float4*)be)[c4];

    float4 o;
    {
        float ln = (z.x - mu) * rstd * g4.x + e4.x;
        float v = ln > 0.f ? ln : 0.01f * ln;
        float gt = 1.f / (1.f + expf(-v));
        o.x = gt * nv.x + (1.f - gt) * cv.x;
    }
    {
        float ln = (z.y - mu) * rstd * g4.y + e4.y;
        float v = ln > 0.f ? ln : 0.01f * ln;
        float gt = 1.f / (1.f + expf(-v));
        o.y = gt * nv.y + (1.f - gt) * cv.y;
    }
    {
        float ln = (z.z - mu) * rstd * g4.z + e4.z;
        float v = ln > 0.f ? ln : 0.01f * ln;
        float gt = 1.f / (1.f + expf(-v));
        o.z = gt * nv.z + (1.f - gt) * cv.z;
    }
    {
        float ln = (z.w - mu) * rstd * g4.w + e4.w;
        float v = ln > 0.f ? ln : 0.01f * ln;
        float gt = 1.f / (1.f + expf(-v));
        o.w = gt * nv.w + (1.f - gt) * cv.w;
    }
    if (row < nrows) ((float4*)(outc + (size_t)row * DD))[c4] = o;
}

// ---------------- final: gather batch rows, metapath fusion, dot score ----------------
__global__ void __launch_bounds__(64) score_kernel(const int* __restrict__ users,
                                                   const int* __restrict__ pos,
                                                   const float* __restrict__ e0u,
                                                   const float* __restrict__ u1,
                                                   const float* __restrict__ u2,
                                                   const float* __restrict__ c1,
                                                   const float* __restrict__ c2,
                                                   const float* __restrict__ e0i,
                                                   const float* __restrict__ i1,
                                                   const float* __restrict__ i2,
                                                   const float* __restrict__ lw,
                                                   const float* __restrict__ mpW,
                                                   const float* __restrict__ mpb,
                                                   const float* __restrict__ mpg,
                                                   const float* __restrict__ mpbe,
                                                   float* __restrict__ out, int B) {
    int b = blockIdx.x;
    if (b >= B) return;
    int t = threadIdx.x;  // 0..63
    __shared__ float fi[128];
    __shared__ float red[4];

    float l0 = lw[0], l1 = lw[1], l2 = lw[2];
    float mx = fmaxf(l0, fmaxf(l1, l2));
    float ex0 = expf(l0 - mx), ex1 = expf(l1 - mx), ex2 = expf(l2 - mx);
    float inv = 1.f / (ex0 + ex1 + ex2);
    float nw0 = ex0 * inv, nw1 = ex1 * inv, nw2 = ex2 * inv;

    int u = users[b], p = pos[b];
    size_t uo = (size_t)u * DD + t;
    size_t po = (size_t)p * DD + t;

    fi[t]      = nw0 * e0u[uo] + nw1 * u1[uo] + nw2 * u2[uo];   // user_weighted
    fi[64 + t] = nw0 * u2[uo]  + nw1 * c1[uo] + nw2 * c2[uo];   // social_weighted
    __syncthreads();

    float z = mpb[t];
#pragma unroll 8
    for (int k = 0; k < 128; ++k) z += fi[k] * __ldg(mpW + k * 64 + t);

    float s = z, q = z * z;
#pragma unroll
    for (int mk = 16; mk; mk >>= 1) {
        s += __shfl_xor_sync(0xffffffffu, s, mk);
        q += __shfl_xor_sync(0xffffffffu, q, mk);
    }
    int wid = t >> 5, lane = t & 31;
    if (lane == 0) { red[wid] = s; red[2 + wid] = q; }
    __syncthreads();
    s = red[0] + red[1];
    q = red[2] + red[3];
    float mu = s * (1.f / 64.f);
    float var = q * (1.f / 64.f) - mu * mu;
    float rstd = rsqrtf(var + 1e-5f);
    float ln = (z - mu) * rstd * mpg[t] + mpbe[t];
    float f = ln > 0.f ? ln : 0.01f * ln;

    float iw = nw0 * e0i[po] + nw1 * i1[po] + nw2 * i2[po];
    float pr = f * iw;
#pragma unroll
    for (int mk = 16; mk; mk >>= 1) pr += __shfl_xor_sync(0xffffffffu, pr, mk);
    __syncthreads();
    if (lane == 0) red[wid] = pr;
    __syncthreads();
    if (t == 0) out[b] = red[0] + red[1];
}

// ---------------- host ----------------
extern "C" void kernel_launch(void* const* d_in, const int* in_sizes, int n_in,
                              void* d_out, int out_size) {
    const int*   users  = (const int*)  d_in[0];
    const int*   pos    = (const int*)  d_in[1];
    const int*   ui_src = (const int*)  d_in[2];
    const int*   ui_dst = (const int*)  d_in[3];
    const float* ui_w   = (const float*)d_in[4];
    const int*   s_src  = (const int*)  d_in[5];
    const int*   s_dst  = (const int*)  d_in[6];
    const float* s_w    = (const float*)d_in[7];
    const float* E0u    = (const float*)d_in[8];
    const float* E0i    = (const float*)d_in[9];
    const float* lw     = (const float*)d_in[10];
    const float* Wsoc   = (const float*)d_in[11];
    const float* hoW    = (const float*)d_in[12];
    const float* hob    = (const float*)d_in[13];
    const float* hog    = (const float*)d_in[14];
    const float* hobe   = (const float*)d_in[15];
    const float* mpW    = (const float*)d_in[16];
    const float* mpb    = (const float*)d_in[17];
    const float* mpg    = (const float*)d_in[18];
    const float* mpbe   = (const float*)d_in[19];

    int B      = in_sizes[0];
    int nnz_ui = in_sizes[4];
    int nnz_s  = in_sizes[7];
    int U      = in_sizes[8] / DD;
    int I      = in_sizes[9] / DD;

    float *u1, *u2, *i1, *i2, *nbr, *c1, *c2;
    int *deg_u, *deg_i, *deg_s, *rp_u, *rp_i, *rp_s, *cur_u, *cur_i, *cur_s, *aux;
    int2 *eu, *ei, *es;
    cudaGetSymbolAddress((void**)&u1,    g_u1);
    cudaGetSymbolAddress((void**)&u2,    g_u2);
    cudaGetSymbolAddress((void**)&i1,    g_i1);
    cudaGetSymbolAddress((void**)&i2,    g_i2);
    cudaGetSymbolAddress((void**)&nbr,   g_nbr);
    cudaGetSymbolAddress((void**)&c1,    g_c1);
    cudaGetSymbolAddress((void**)&c2,    g_c2);
    cudaGetSymbolAddress((void**)&deg_u, g_deg_u);
    cudaGetSymbolAddress((void**)&deg_i, g_deg_i);
    cudaGetSymbolAddress((void**)&deg_s, g_deg_s);
    cudaGetSymbolAddress((void**)&rp_u,  g_rp_u);
    cudaGetSymbolAddress((void**)&rp_i,  g_rp_i);
    cudaGetSymbolAddress((void**)&rp_s,  g_rp_s);
    cudaGetSymbolAddress((void**)&cur_u, g_cur_u);
    cudaGetSymbolAddress((void**)&cur_i, g_cur_i);
    cudaGetSymbolAddress((void**)&cur_s, g_cur_s);
    cudaGetSymbolAddress((void**)&aux,   g_aux);
    cudaGetSymbolAddress((void**)&eu,    g_eu);
    cudaGetSymbolAddress((void**)&ei,    g_ei);
    cudaGetSymbolAddress((void**)&es,    g_es);

    int ge_ui = (nnz_ui + 255) / 256;
    int ge_s  = (nnz_s + 255) / 256;
    int nbU = (U + 1023) / 1024, nbI = (I + 1023) / 1024;
    int gU = (U + 255) / 256, gI = (I + 255) / 256;
    int g_gu = (U + 7) / 8, g_gi = (I + 7) / 8;
    int g_rows = (U + 31) / 32;

    // ---- CSR build ----
    cudaMemsetAsync(deg_u, 0, (size_t)U * sizeof(int));
    cudaMemsetAsync(deg_i, 0, (size_t)I * sizeof(int));
    cudaMemsetAsync(deg_s, 0, (size_t)U * sizeof(int));
    count_ui_kernel<<<ge_ui, 256>>>(ui_src, ui_dst, deg_u, deg_i, nnz_ui);
    count_s_kernel<<<ge_s, 256>>>(s_src, deg_s, nnz_s);

    scan1_kernel<<<nbU, 1024>>>(deg_u, rp_u, aux, U);
    scan2_kernel<<<1, 256>>>(aux, nbU);
    scan3_kernel<<<gU, 256>>>(rp_u, aux, cur_u, U, nnz_ui);

    scan1_kernel<<<nbI, 1024>>>(deg_i, rp_i, aux, I);
    scan2_kernel<<<1, 256>>>(aux, nbI);
    scan3_kernel<<<gI, 256>>>(rp_i, aux, cur_i, I, nnz_ui);

    scan1_kernel<<<nbU, 1024>>>(deg_s, rp_s, aux, U);
    scan2_kernel<<<1, 256>>>(aux, nbU);
    scan3_kernel<<<gU, 256>>>(rp_s, aux, cur_s, U, nnz_s);

    scatter_ui_kernel<<<ge_ui, 256>>>(ui_src, ui_dst, ui_w, cur_u, cur_i, eu, ei, nnz_ui);
    scatter_s_kernel<<<ge_s, 256>>>(s_src, s_dst, s_w, cur_s, es, nnz_s);

    // ---- LightGCN layer 1 (residual folded into gather init) ----
    gather_kernel<<<g_gu, 256>>>(rp_u, eu, E0i, E0u, 0.1f, u1, U);
    gather_kernel<<<g_gi, 256>>>(rp_i, ei, E0u, E0i, 0.1f, i1, I);

    // ---- LightGCN layer 2 ----
    gather_kernel<<<g_gu, 256>>>(rp_u, eu, i1, E0u, 0.1f, u2, U);
    gather_kernel<<<g_gi, 256>>>(rp_i, ei, u1, E0i, 0.1f, i2, I);

    // ---- Social layer 1 (cur = u2): nbr0 = A@cur, GEMM fused into gate ----
    gather_kernel<<<g_gu, 256>>>(rp_s, es, u2, (const float*)0, 0.f, nbr, U);
    social_gate2_kernel<<<g_rows, 512>>>(u2, nbr, Wsoc, hoW, hob, hog, hobe, c1, U);

    // ---- Social layer 2 (cur = c1) ----
    gather_kernel<<<g_gu, 256>>>(rp_s, es, c1, (const float*)0, 0.f, nbr, U);
    social_gate2_kernel<<<g_rows, 512>>>(c1, nbr, Wsoc + 64 * 64, hoW, hob, hog, hobe, c2, U);

    // ---- Fusion + scoring, batch rows only ----
    score_kernel<<<B, 64>>>(users, pos, E0u, u1, u2, c1, c2, E0i, i1, i2,
                            lw, mpW, mpb, mpg, mpbe, (float*)d_out, B);
}